// round 15
// baseline (speedup 1.0000x reference)
#include <cuda_runtime.h>
#include <math.h>

#define NB   16
#define NL   1024
#define ND   512
#define NDH  64
#define KTOP 13

// Scratch (no allocations allowed): 4 x 4MB fp32
__device__ float g_qp[NB * NDH * NL];   // q projection, [b][d][l]
__device__ float g_kp[NB * NDH * NL];   // k projection, [b][d][l]
__device__ float g_vp[NB * NDH * NL];   // v projection, [b][d][l]
__device__ float g_agg[NB * NDH * NL];  // aggregated result, [b][d][l]

// ---- bf16 split helpers (truncation split) --------------------------------
__device__ __forceinline__ void split_dup(float x, unsigned& wh, unsigned& wl) {
    unsigned u = __float_as_uint(x);
    float hi = __uint_as_float(u & 0xFFFF0000u);
    unsigned lu = __float_as_uint(x - hi);
    wh = __byte_perm(u,  u,  0x3232);
    wl = __byte_perm(lu, lu, 0x3232);
}
__device__ __forceinline__ unsigned split_pack(float x) {
    unsigned u = __float_as_uint(x);
    float hi = __uint_as_float(u & 0xFFFF0000u);
    unsigned lu = __float_as_uint(x - hi);
    return __byte_perm(u, lu, 0x7632);
}

__device__ __forceinline__ void mma_bf16(float* c, const unsigned* a,
                                         unsigned b0, unsigned b1) {
    asm volatile(
        "mma.sync.aligned.m16n8k16.row.col.f32.bf16.bf16.f32 "
        "{%0,%1,%2,%3}, {%4,%5,%6,%7}, {%8,%9}, {%0,%1,%2,%3};\n"
        : "+f"(c[0]), "+f"(c[1]), "+f"(c[2]), "+f"(c[3])
        : "r"(a[0]), "r"(a[1]), "r"(a[2]), "r"(a[3]), "r"(b0), "r"(b1));
}

__device__ __forceinline__ int smidx(int row, int w) {
    return row * 32 + (((w >> 3) ^ (row & 3)) << 3)
         + ((w & 7) ^ (((row >> 2) & 1) << 2));
}

// ---------------------------------------------------------------------------
// Kernel 1: projection via bf16 tensor cores, split-K doubling.
// R7 exact (best measured). BK=32, single-buffered static smem,
// register prefetch. grid (NL/128, NB, 3), 256 threads.
// ---------------------------------------------------------------------------
__global__ __launch_bounds__(256) void proj_kernel(
    const float* __restrict__ Q, const float* __restrict__ K,
    const float* __restrict__ V, const float* __restrict__ Wq,
    const float* __restrict__ bq)
{
    __shared__ unsigned Ws[64 * 32];
    __shared__ unsigned Xh[128 * 32];
    __shared__ unsigned Xl[128 * 32];

    const int b    = blockIdx.y;
    const int l0   = blockIdx.x * 128;
    const int mat  = blockIdx.z;
    const int tid  = threadIdx.x;
    const int wid  = tid >> 5;
    const int lane = tid & 31;
    const int g    = lane >> 2;
    const int cq   = lane & 3;
    const int m_base = (wid >> 2) * 32;
    const int n_base = (wid & 3) * 32;

    const float* src = (mat == 0 ? Q : (mat == 1 ? K : V))
                     + ((size_t)b * NL + l0) * ND;
    float* dst = (mat == 0 ? g_qp : (mat == 1 ? g_kp : g_vp))
               + (size_t)b * NDH * NL + l0;

    int xgb[4], xsb[4];
    #pragma unroll
    for (int i = 0; i < 4; ++i) {
        int f4id = tid + i * 256;
        int r    = f4id >> 3;
        int c4   = f4id & 7;
        xgb[i]   = r * ND + c4 * 4;
        xsb[i]   = r * 32 + (((c4 >> 1) ^ (r & 3)) << 3)
                 + (((c4 & 1) << 2) ^ (((r >> 2) & 1) << 2));
    }
    int wdd[2], wkq[2], wsb[2];
    #pragma unroll
    for (int i = 0; i < 2; ++i) {
        int qid = tid + i * 256;
        wdd[i]  = qid & 63;
        wkq[i]  = qid >> 6;
        wsb[i]  = wdd[i] * 32 + (((wkq[i] >> 1) ^ (wdd[i] & 3)) << 3)
                + (((wkq[i] & 1) << 2) ^ (((wdd[i] >> 2) & 1) << 2));
    }

    float acc[2][4][4];
    #pragma unroll
    for (int mt = 0; mt < 2; ++mt)
        #pragma unroll
        for (int nt = 0; nt < 4; ++nt)
            #pragma unroll
            for (int r = 0; r < 4; ++r) acc[mt][nt][r] = 0.f;

    float4 xR[4];
    float  wF[8];
    #pragma unroll
    for (int i = 0; i < 4; ++i)
        xR[i] = *reinterpret_cast<const float4*>(src + xgb[i]);
    #pragma unroll
    for (int i = 0; i < 2; ++i)
        #pragma unroll
        for (int j = 0; j < 4; ++j)
            wF[i * 4 + j] = Wq[(size_t)(wkq[i] * 4 + j) * NDH + wdd[i]];

    for (int ch = 0; ch < 16; ++ch) {
        #pragma unroll
        for (int i = 0; i < 4; ++i) {
            unsigned h0,h1,h2,h3, q0,q1,q2,q3;
            split_dup(xR[i].x, h0, q0);
            split_dup(xR[i].y, h1, q1);
            split_dup(xR[i].z, h2, q2);
            split_dup(xR[i].w, h3, q3);
            *reinterpret_cast<uint4*>(&Xh[xsb[i]]) = make_uint4(h0,h1,h2,h3);
            *reinterpret_cast<uint4*>(&Xl[xsb[i]]) = make_uint4(q0,q1,q2,q3);
        }
        #pragma unroll
        for (int i = 0; i < 2; ++i) {
            *reinterpret_cast<uint4*>(&Ws[wsb[i]]) = make_uint4(
                split_pack(wF[i*4+0]), split_pack(wF[i*4+1]),
                split_pack(wF[i*4+2]), split_pack(wF[i*4+3]));
        }
        __syncthreads();

        if (ch < 15) {
            const int ko = (ch + 1) * 32;
            #pragma unroll
            for (int i = 0; i < 4; ++i)
                xR[i] = *reinterpret_cast<const float4*>(src + xgb[i] + ko);
            #pragma unroll
            for (int i = 0; i < 2; ++i)
                #pragma unroll
                for (int j = 0; j < 4; ++j)
                    wF[i * 4 + j] = Wq[(size_t)(ko + wkq[i] * 4 + j) * NDH + wdd[i]];
        }

        #pragma unroll
        for (int ks = 0; ks < 4; ++ks) {
            unsigned a[2][4];
            #pragma unroll
            for (int mt = 0; mt < 2; ++mt) {
                int r0 = m_base + mt * 16 + g;
                a[mt][0] = Ws[smidx(r0,     ks * 8 + cq)];
                a[mt][1] = Ws[smidx(r0 + 8, ks * 8 + cq)];
                a[mt][2] = Ws[smidx(r0,     ks * 8 + cq + 4)];
                a[mt][3] = Ws[smidx(r0 + 8, ks * 8 + cq + 4)];
            }
            #pragma unroll
            for (int nt = 0; nt < 4; ++nt) {
                int rn = n_base + nt * 8 + g;
                unsigned bh0 = Xh[smidx(rn, ks * 8 + cq)];
                unsigned bh1 = Xh[smidx(rn, ks * 8 + cq + 4)];
                unsigned bl0 = Xl[smidx(rn, ks * 8 + cq)];
                unsigned bl1 = Xl[smidx(rn, ks * 8 + cq + 4)];
                #pragma unroll
                for (int mt = 0; mt < 2; ++mt) {
                    mma_bf16(acc[mt][nt], a[mt], bh0, bh1);
                    mma_bf16(acc[mt][nt], a[mt], bl0, bl1);
                }
            }
        }
        __syncthreads();
    }

    #pragma unroll
    for (int mt = 0; mt < 2; ++mt) {
        int d0 = m_base + mt * 16 + g;
        float bLo = bq[d0];
        float bHi = bq[d0 + 8];
        #pragma unroll
        for (int nt = 0; nt < 4; ++nt) {
            int l = n_base + nt * 8 + 2 * cq;
            float2 r0 = make_float2(acc[mt][nt][0] + bLo, acc[mt][nt][1] + bLo);
            float2 r1 = make_float2(acc[mt][nt][2] + bHi, acc[mt][nt][3] + bHi);
            *reinterpret_cast<float2*>(dst + (size_t)d0 * NL + l)       = r0;
            *reinterpret_cast<float2*>(dst + (size_t)(d0 + 8) * NL + l) = r1;
        }
    }
}

// ---------------------------------------------------------------------------
// Kernel 2: corr via FFT (reference algorithm):
//   corr = real(ifft(fft(q) * conj(fft(k))))
// Two series per CTA, 256 threads, fused radix-2^2 double stages (R14).
// NEW top-13: warp-local register-resident selection (no barriers, no smem
// rescans) -> 52 candidates/series -> single-warp shuffle merge.
// ---------------------------------------------------------------------------
__global__ __launch_bounds__(256) void corr_kernel()
{
    __shared__ __align__(16) float2 fbuf[4096];   // 32 KB workspace
    __shared__ float2 tw[512];
    __shared__ float s_tv[2][KTOP];
    __shared__ int   s_ti[2][KTOP];
    __shared__ float s_w[2][KTOP];
    __shared__ float candv[2][52];
    __shared__ int   candi[2][52];

    const int b   = blockIdx.y;
    const int d0  = blockIdx.x * 2;
    const int tid = threadIdx.x;
    float* fbf = reinterpret_cast<float*>(fbuf);
    const size_t offA = ((size_t)b * NDH + d0) * NL;

    for (int j = tid; j < 512; j += 256) {
        float s, c;
        sincospif(-(float)j / 512.0f, &s, &c);
        tw[j] = make_float2(c, s);
    }
    {
        const float4* qa = reinterpret_cast<const float4*>(g_qp + offA);
        const float4* ka = reinterpret_cast<const float4*>(g_kp + offA);
        for (int i = tid; i < 512; i += 256) {
            float4 q = qa[i], k = ka[i];
            int o = i * 4;
            fbuf[o+0] = make_float2(q.x, k.x);
            fbuf[o+1] = make_float2(q.y, k.y);
            fbuf[o+2] = make_float2(q.z, k.z);
            fbuf[o+3] = make_float2(q.w, k.w);
        }
    }
    __syncthreads();

    // forward FFT, both series, 5 fused double-stages, ping-pong 0<->2048.
    int src = 0;
    for (int fs = 0; fs < 5; ++fs) {
        const int s  = 1 << (2 * fs);
        const int s2 = s << 1;
        const int dst = src ^ 2048;
        #pragma unroll 2
        for (int it = 0; it < 2; ++it) {
            int t  = tid + it * 256;
            int so = (t >> 8) << 10;
            int u  = t & 255;
            int j  = u & ~(s - 1);
            float2 x0 = fbuf[src + so + u];
            float2 x1 = fbuf[src + so + u + 256];
            float2 x2 = fbuf[src + so + u + 512];
            float2 x3 = fbuf[src + so + u + 768];
            float2 w0 = tw[j];
            float2 w1 = tw[j + 256];
            float2 y0 = make_float2(x0.x + x2.x, x0.y + x2.y);
            float2 dA = make_float2(x0.x - x2.x, x0.y - x2.y);
            float2 y1 = make_float2(w0.x*dA.x - w0.y*dA.y, w0.x*dA.y + w0.y*dA.x);
            float2 y2 = make_float2(x1.x + x3.x, x1.y + x3.y);
            float2 dB = make_float2(x1.x - x3.x, x1.y - x3.y);
            float2 y3 = make_float2(w1.x*dB.x - w1.y*dB.y, w1.x*dB.y + w1.y*dB.x);
            int a  = u + j;
            int ja = a & ~(s2 - 1);
            int jb = (a + s) & ~(s2 - 1);
            float2 wa = tw[ja];
            float2 wb = tw[jb];
            float2 dC = make_float2(y0.x - y2.x, y0.y - y2.y);
            fbuf[dst + so + a + ja]      = make_float2(y0.x + y2.x, y0.y + y2.y);
            fbuf[dst + so + a + ja + s2] =
                make_float2(wa.x*dC.x - wa.y*dC.y, wa.x*dC.y + wa.y*dC.x);
            float2 dD = make_float2(y1.x - y3.x, y1.y - y3.y);
            fbuf[dst + so + a + s + jb]      = make_float2(y1.x + y3.x, y1.y + y3.y);
            fbuf[dst + so + a + s + jb + s2] =
                make_float2(wb.x*dD.x - wb.y*dD.y, wb.x*dD.y + wb.y*dD.x);
        }
        __syncthreads();
        src = dst;
    }
    // forward result in [2048, 4096)

    // spectral: S = Q * conj(K); T = S_a + i*S_b; write conj(T) to [0,1024)
    for (int it = 0; it < 4; ++it) {
        int f  = tid + it * 256;
        int fn = (1024 - f) & 1023;
        float2 Za = fbuf[2048 + f],  Zan = fbuf[2048 + fn];
        float2 Zb = fbuf[3072 + f],  Zbn = fbuf[3072 + fn];
        float qx = 0.5f*(Za.x + Zan.x), qy = 0.5f*(Za.y - Zan.y);
        float kx = 0.5f*(Za.y + Zan.y), ky = -0.5f*(Za.x - Zan.x);
        float sax = qx*kx + qy*ky, say = qy*kx - qx*ky;
        float qx2 = 0.5f*(Zb.x + Zbn.x), qy2 = 0.5f*(Zb.y - Zbn.y);
        float kx2 = 0.5f*(Zb.y + Zbn.y), ky2 = -0.5f*(Zb.x - Zbn.x);
        float sbx = qx2*kx2 + qy2*ky2, sby = qy2*kx2 - qx2*ky2;
        fbuf[f] = make_float2(sax - sby, -(say + sbx));
    }
    __syncthreads();

    // load v for both series into floats [6144,8192)
    {
        const float4* va = reinterpret_cast<const float4*>(g_vp + offA);
        for (int i = tid; i < 512; i += 256)
            *reinterpret_cast<float4*>(&fbf[6144 + i * 4]) = va[i];
    }

    // inverse FFT (forward FFT of conj T), 5 fused double-stages,
    // ping-pong [0,1024) <-> [2048,3072). Ends in [2048,3072).
    int s2v = 0;
    for (int fs = 0; fs < 5; ++fs) {
        const int s  = 1 << (2 * fs);
        const int s2 = s << 1;
        const int dst = (s2v == 0) ? 2048 : 0;
        {
            int u  = tid;
            int j  = u & ~(s - 1);
            float2 x0 = fbuf[s2v + u];
            float2 x1 = fbuf[s2v + u + 256];
            float2 x2 = fbuf[s2v + u + 512];
            float2 x3 = fbuf[s2v + u + 768];
            float2 w0 = tw[j];
            float2 w1 = tw[j + 256];
            float2 y0 = make_float2(x0.x + x2.x, x0.y + x2.y);
            float2 dA = make_float2(x0.x - x2.x, x0.y - x2.y);
            float2 y1 = make_float2(w0.x*dA.x - w0.y*dA.y, w0.x*dA.y + w0.y*dA.x);
            float2 y2 = make_float2(x1.x + x3.x, x1.y + x3.y);
            float2 dB = make_float2(x1.x - x3.x, x1.y - x3.y);
            float2 y3 = make_float2(w1.x*dB.x - w1.y*dB.y, w1.x*dB.y + w1.y*dB.x);
            int a  = u + j;
            int ja = a & ~(s2 - 1);
            int jb = (a + s) & ~(s2 - 1);
            float2 wa = tw[ja];
            float2 wb = tw[jb];
            float2 dC = make_float2(y0.x - y2.x, y0.y - y2.y);
            fbuf[dst + a + ja]      = make_float2(y0.x + y2.x, y0.y + y2.y);
            fbuf[dst + a + ja + s2] =
                make_float2(wa.x*dC.x - wa.y*dC.y, wa.x*dC.y + wa.y*dC.x);
            float2 dD = make_float2(y1.x - y3.x, y1.y - y3.y);
            fbuf[dst + a + s + jb]      = make_float2(y1.x + y3.x, y1.y + y3.y);
            fbuf[dst + a + s + jb + s2] =
                make_float2(wb.x*dD.x - wb.y*dD.y, wb.x*dD.y + wb.y*dD.x);
        }
        __syncthreads();
        s2v = dst;
    }
    // result in [2048,3072): corr_a = Re/N, corr_b = -Im/N

    const float invN = 1.0f / 1024.0f;
    for (int it = 0; it < 4; ++it) {
        int n = tid + it * 256;
        float2 F = fbuf[2048 + n];
        fbf[n]        =  F.x * invN;
        fbf[1024 + n] = -F.y * invN;
    }
    __syncthreads();

    // ---- top-13, warp-local register selection ----
    // warps 0-3 -> series A (lags 0..1023), warps 4-7 -> series B
    const int wid5 = tid >> 5;
    const int lane = tid & 31;
    const int sidw = wid5 >> 2;        // series for selection
    const int ws   = wid5 & 3;         // warp within series
    {
        const float* scw = fbf + (sidw << 10) + ws * 256;
        float lv[8];
        #pragma unroll
        for (int j = 0; j < 8; ++j) lv[j] = scw[lane * 8 + j];
        const int gbase = ws * 256 + lane * 8;

        #pragma unroll
        for (int p = 0; p < KTOP; ++p) {
            float bv = lv[0]; int bj = 0;
            #pragma unroll
            for (int j = 1; j < 8; ++j)
                if (lv[j] > bv) { bv = lv[j]; bj = j; }   // asc -> lowest idx
            int bi = gbase + bj;
            #pragma unroll
            for (int off = 16; off > 0; off >>= 1) {
                float ov = __shfl_xor_sync(0xffffffffu, bv, off);
                int   oi = __shfl_xor_sync(0xffffffffu, bi, off);
                if (ov > bv || (ov == bv && oi < bi)) { bv = ov; bi = oi; }
            }
            if (lane == 0) {
                candv[sidw][ws * 13 + p] = bv;
                candi[sidw][ws * 13 + p] = bi;
            }
            if (((bi - ws * 256) >> 3) == lane) lv[bi & 7] = -3.4e38f;
        }
    }
    __syncthreads();

    // merge 52 -> 13 per series (warp 0 for A, warp 4 for B), then softmax
    if (ws == 0) {
        float mv0 = (lane < 52) ? candv[sidw][lane] : -3.4e38f;
        int   mi0 = (lane < 52) ? candi[sidw][lane] : (1 << 30);
        float mv1 = (lane + 32 < 52) ? candv[sidw][lane + 32] : -3.4e38f;
        int   mi1 = (lane + 32 < 52) ? candi[sidw][lane + 32] : (1 << 30);
        #pragma unroll
        for (int p = 0; p < KTOP; ++p) {
            float bv = mv0; int bi = mi0;
            if (mv1 > bv || (mv1 == bv && mi1 < bi)) { bv = mv1; bi = mi1; }
            #pragma unroll
            for (int off = 16; off > 0; off >>= 1) {
                float ov = __shfl_xor_sync(0xffffffffu, bv, off);
                int   oi = __shfl_xor_sync(0xffffffffu, bi, off);
                if (ov > bv || (ov == bv && oi < bi)) { bv = ov; bi = oi; }
            }
            if (lane == 0) { s_tv[sidw][p] = bv; s_ti[sidw][p] = bi; }
            if (mi0 == bi) mv0 = -3.4e38f;
            if (mi1 == bi) mv1 = -3.4e38f;
        }
        if (lane == 0) {
            float mx = s_tv[sidw][0];
            float e[KTOP], sum = 0.f;
            #pragma unroll
            for (int p = 0; p < KTOP; ++p) {
                e[p] = expf(s_tv[sidw][p] - mx); sum += e[p];
            }
            float inv = 1.0f / sum;
            #pragma unroll
            for (int p = 0; p < KTOP; ++p) s_w[sidw][p] = e[p] * inv;
        }
    }
    __syncthreads();

    // agg[l] = sum_k w_k * v[(l + idx_k) & 1023]
    const int sid = tid >> 7;
    const int lt  = tid & 127;
    const float* sv = fbf + 6144 + (sid << 10);
    float* aggrow = g_agg + offA + (size_t)sid * NL;
    float wgt[KTOP]; int ix[KTOP];
    #pragma unroll
    for (int p = 0; p < KTOP; ++p) { wgt[p] = s_w[sid][p]; ix[p] = s_ti[sid][p]; }
    #pragma unroll
    for (int jj = 0; jj < 8; ++jj) {
        int l = lt + jj * 128;
        float acc = 0.f;
        #pragma unroll
        for (int p = 0; p < KTOP; ++p)
            acc += wgt[p] * sv[(l + ix[p]) & 1023];
        aggrow[l] = acc;
    }
}

// ---------------------------------------------------------------------------
// Kernel 3: transpose-broadcast agg[b][d][l] -> out[b][l][h*64+d], h=0..7.
// Staging now [l][d] so the store loop is one conflict-free LDS.128 per f4.
// ---------------------------------------------------------------------------
__global__ __launch_bounds__(256) void out_kernel(float* __restrict__ out)
{
    __shared__ float t[32][68];   // [l][d], pad 4 (keeps 16B alignment)
    const int b   = blockIdx.y;
    const int l0  = blockIdx.x * 32;
    const int tid = threadIdx.x;
    const float* agg = g_agg + (size_t)b * NDH * NL;

    #pragma unroll
    for (int i = 0; i < 8; ++i) {
        int flat = tid + i * 256;   // 2048 = 64 d x 32 l
        int dd   = flat >> 5;
        int ll   = flat & 31;
        t[ll][dd] = agg[(size_t)dd * NL + l0 + ll];   // coalesced LDG
    }
    __syncthreads();

    float* obase = out + ((size_t)b * NL + l0) * (NDH * 8);
    #pragma unroll
    for (int i = 0; i < 16; ++i) {
        int f4  = tid + i * 256;    // 4096 float4 = 32 l x 128 ch4
        int ll  = f4 >> 7;
        int c0  = (f4 & 127) * 4;
        float4 v = *reinterpret_cast<const float4*>(&t[ll][c0 & 63]);  // LDS.128
        *reinterpret_cast<float4*>(obase + (size_t)ll * 512 + c0) = v;
    }
}

// ---------------------------------------------------------------------------
extern "C" void kernel_launch(void* const* d_in, const int* in_sizes, int n_in,
                              void* d_out, int out_size)
{
    const float* Q  = (const float*)d_in[0];
    const float* K  = (const float*)d_in[1];
    const float* V  = (const float*)d_in[2];
    const float* Wq = (const float*)d_in[3];
    const float* bq = (const float*)d_in[4];
    float* out = (float*)d_out;

    proj_kernel<<<dim3(NL / 128, NB, 3), 256>>>(Q, K, V, Wq, bq);
    corr_kernel<<<dim3(NDH / 2, NB), 256>>>();
    out_kernel<<<dim3(NL / 32, NB), 256>>>(out);
}

// round 16
// speedup vs baseline: 1.0155x; 1.0155x over previous
#include <cuda_runtime.h>
#include <math.h>

#define NB   16
#define NL   1024
#define ND   512
#define NDH  64
#define KTOP 13

// Scratch (no allocations allowed): 4 x 4MB fp32
__device__ float g_qp[NB * NDH * NL];   // q projection, [b][d][l]
__device__ float g_kp[NB * NDH * NL];   // k projection, [b][d][l]
__device__ float g_vp[NB * NDH * NL];   // v projection, [b][d][l]
__device__ float g_agg[NB * NDH * NL];  // aggregated result, [b][d][l]

// ---- bf16 split helpers (truncation split) --------------------------------
__device__ __forceinline__ void split_dup(float x, unsigned& wh, unsigned& wl) {
    unsigned u = __float_as_uint(x);
    float hi = __uint_as_float(u & 0xFFFF0000u);
    unsigned lu = __float_as_uint(x - hi);
    wh = __byte_perm(u,  u,  0x3232);
    wl = __byte_perm(lu, lu, 0x3232);
}
__device__ __forceinline__ unsigned split_pack(float x) {
    unsigned u = __float_as_uint(x);
    float hi = __uint_as_float(u & 0xFFFF0000u);
    unsigned lu = __float_as_uint(x - hi);
    return __byte_perm(u, lu, 0x7632);
}

__device__ __forceinline__ void mma_bf16(float* c, const unsigned* a,
                                         unsigned b0, unsigned b1) {
    asm volatile(
        "mma.sync.aligned.m16n8k16.row.col.f32.bf16.bf16.f32 "
        "{%0,%1,%2,%3}, {%4,%5,%6,%7}, {%8,%9}, {%0,%1,%2,%3};\n"
        : "+f"(c[0]), "+f"(c[1]), "+f"(c[2]), "+f"(c[3])
        : "r"(a[0]), "r"(a[1]), "r"(a[2]), "r"(a[3]), "r"(b0), "r"(b1));
}

__device__ __forceinline__ int smidx(int row, int w) {
    return row * 32 + (((w >> 3) ^ (row & 3)) << 3)
         + ((w & 7) ^ (((row >> 2) & 1) << 2));
}

// ---------------------------------------------------------------------------
// Kernel 1: projection via bf16 tensor cores, split-K doubling.
// R7 structure; MMA issue order batch-reordered: all hi-plane MMAs (16
// independent accumulators), THEN all lo-plane MMAs -> the acc RAW chain
// (hi->lo on same accumulator) is covered by 16 intervening issues.
// Per-accumulator order (hi then lo) unchanged => bitwise-identical output.
// ---------------------------------------------------------------------------
__global__ __launch_bounds__(256) void proj_kernel(
    const float* __restrict__ Q, const float* __restrict__ K,
    const float* __restrict__ V, const float* __restrict__ Wq,
    const float* __restrict__ bq)
{
    __shared__ unsigned Ws[64 * 32];
    __shared__ unsigned Xh[128 * 32];
    __shared__ unsigned Xl[128 * 32];

    const int b    = blockIdx.y;
    const int l0   = blockIdx.x * 128;
    const int mat  = blockIdx.z;
    const int tid  = threadIdx.x;
    const int wid  = tid >> 5;
    const int lane = tid & 31;
    const int g    = lane >> 2;
    const int cq   = lane & 3;
    const int m_base = (wid >> 2) * 32;
    const int n_base = (wid & 3) * 32;

    const float* src = (mat == 0 ? Q : (mat == 1 ? K : V))
                     + ((size_t)b * NL + l0) * ND;
    float* dst = (mat == 0 ? g_qp : (mat == 1 ? g_kp : g_vp))
               + (size_t)b * NDH * NL + l0;

    int xgb[4], xsb[4];
    #pragma unroll
    for (int i = 0; i < 4; ++i) {
        int f4id = tid + i * 256;
        int r    = f4id >> 3;
        int c4   = f4id & 7;
        xgb[i]   = r * ND + c4 * 4;
        xsb[i]   = r * 32 + (((c4 >> 1) ^ (r & 3)) << 3)
                 + (((c4 & 1) << 2) ^ (((r >> 2) & 1) << 2));
    }
    int wdd[2], wkq[2], wsb[2];
    #pragma unroll
    for (int i = 0; i < 2; ++i) {
        int qid = tid + i * 256;
        wdd[i]  = qid & 63;
        wkq[i]  = qid >> 6;
        wsb[i]  = wdd[i] * 32 + (((wkq[i] >> 1) ^ (wdd[i] & 3)) << 3)
                + (((wkq[i] & 1) << 2) ^ (((wdd[i] >> 2) & 1) << 2));
    }

    float acc[2][4][4];
    #pragma unroll
    for (int mt = 0; mt < 2; ++mt)
        #pragma unroll
        for (int nt = 0; nt < 4; ++nt)
            #pragma unroll
            for (int r = 0; r < 4; ++r) acc[mt][nt][r] = 0.f;

    float4 xR[4];
    float  wF[8];
    #pragma unroll
    for (int i = 0; i < 4; ++i)
        xR[i] = *reinterpret_cast<const float4*>(src + xgb[i]);
    #pragma unroll
    for (int i = 0; i < 2; ++i)
        #pragma unroll
        for (int j = 0; j < 4; ++j)
            wF[i * 4 + j] = Wq[(size_t)(wkq[i] * 4 + j) * NDH + wdd[i]];

    for (int ch = 0; ch < 16; ++ch) {
        #pragma unroll
        for (int i = 0; i < 4; ++i) {
            unsigned h0,h1,h2,h3, q0,q1,q2,q3;
            split_dup(xR[i].x, h0, q0);
            split_dup(xR[i].y, h1, q1);
            split_dup(xR[i].z, h2, q2);
            split_dup(xR[i].w, h3, q3);
            *reinterpret_cast<uint4*>(&Xh[xsb[i]]) = make_uint4(h0,h1,h2,h3);
            *reinterpret_cast<uint4*>(&Xl[xsb[i]]) = make_uint4(q0,q1,q2,q3);
        }
        #pragma unroll
        for (int i = 0; i < 2; ++i) {
            *reinterpret_cast<uint4*>(&Ws[wsb[i]]) = make_uint4(
                split_pack(wF[i*4+0]), split_pack(wF[i*4+1]),
                split_pack(wF[i*4+2]), split_pack(wF[i*4+3]));
        }
        __syncthreads();

        if (ch < 15) {
            const int ko = (ch + 1) * 32;
            #pragma unroll
            for (int i = 0; i < 4; ++i)
                xR[i] = *reinterpret_cast<const float4*>(src + xgb[i] + ko);
            #pragma unroll
            for (int i = 0; i < 2; ++i)
                #pragma unroll
                for (int j = 0; j < 4; ++j)
                    wF[i * 4 + j] = Wq[(size_t)(ko + wkq[i] * 4 + j) * NDH + wdd[i]];
        }

        #pragma unroll
        for (int ks = 0; ks < 4; ++ks) {
            unsigned a[2][4];
            #pragma unroll
            for (int mt = 0; mt < 2; ++mt) {
                int r0 = m_base + mt * 16 + g;
                a[mt][0] = Ws[smidx(r0,     ks * 8 + cq)];
                a[mt][1] = Ws[smidx(r0 + 8, ks * 8 + cq)];
                a[mt][2] = Ws[smidx(r0,     ks * 8 + cq + 4)];
                a[mt][3] = Ws[smidx(r0 + 8, ks * 8 + cq + 4)];
            }
            unsigned bh0[4], bh1[4], bl0[4], bl1[4];
            #pragma unroll
            for (int nt = 0; nt < 4; ++nt) {
                int rn = n_base + nt * 8 + g;
                bh0[nt] = Xh[smidx(rn, ks * 8 + cq)];
                bh1[nt] = Xh[smidx(rn, ks * 8 + cq + 4)];
                bl0[nt] = Xl[smidx(rn, ks * 8 + cq)];
                bl1[nt] = Xl[smidx(rn, ks * 8 + cq + 4)];
            }
            // all hi-plane MMAs first (8 independent accumulators) ...
            #pragma unroll
            for (int nt = 0; nt < 4; ++nt)
                #pragma unroll
                for (int mt = 0; mt < 2; ++mt)
                    mma_bf16(acc[mt][nt], a[mt], bh0[nt], bh1[nt]);
            // ... then all lo-plane MMAs (RAW gap = 8 issued instructions)
            #pragma unroll
            for (int nt = 0; nt < 4; ++nt)
                #pragma unroll
                for (int mt = 0; mt < 2; ++mt)
                    mma_bf16(acc[mt][nt], a[mt], bl0[nt], bl1[nt]);
        }
        __syncthreads();
    }

    #pragma unroll
    for (int mt = 0; mt < 2; ++mt) {
        int d0 = m_base + mt * 16 + g;
        float bLo = bq[d0];
        float bHi = bq[d0 + 8];
        #pragma unroll
        for (int nt = 0; nt < 4; ++nt) {
            int l = n_base + nt * 8 + 2 * cq;
            float2 r0 = make_float2(acc[mt][nt][0] + bLo, acc[mt][nt][1] + bLo);
            float2 r1 = make_float2(acc[mt][nt][2] + bHi, acc[mt][nt][3] + bHi);
            *reinterpret_cast<float2*>(dst + (size_t)d0 * NL + l)       = r0;
            *reinterpret_cast<float2*>(dst + (size_t)(d0 + 8) * NL + l) = r1;
        }
    }
}

// ---------------------------------------------------------------------------
// Kernel 2: corr via FFT (reference algorithm):
//   corr = real(ifft(fft(q) * conj(fft(k))))
// Two series per CTA, 256 threads, fused radix-2^2 double stages.
// Warp-local register top-13 -> 52 candidates -> single-warp merge.
// (R14/R15 best; unchanged)
// ---------------------------------------------------------------------------
__global__ __launch_bounds__(256) void corr_kernel()
{
    __shared__ __align__(16) float2 fbuf[4096];   // 32 KB workspace
    __shared__ float2 tw[512];
    __shared__ float s_tv[2][KTOP];
    __shared__ int   s_ti[2][KTOP];
    __shared__ float s_w[2][KTOP];
    __shared__ float candv[2][52];
    __shared__ int   candi[2][52];

    const int b   = blockIdx.y;
    const int d0  = blockIdx.x * 2;
    const int tid = threadIdx.x;
    float* fbf = reinterpret_cast<float*>(fbuf);
    const size_t offA = ((size_t)b * NDH + d0) * NL;

    for (int j = tid; j < 512; j += 256) {
        float s, c;
        sincospif(-(float)j / 512.0f, &s, &c);
        tw[j] = make_float2(c, s);
    }
    {
        const float4* qa = reinterpret_cast<const float4*>(g_qp + offA);
        const float4* ka = reinterpret_cast<const float4*>(g_kp + offA);
        for (int i = tid; i < 512; i += 256) {
            float4 q = qa[i], k = ka[i];
            int o = i * 4;
            fbuf[o+0] = make_float2(q.x, k.x);
            fbuf[o+1] = make_float2(q.y, k.y);
            fbuf[o+2] = make_float2(q.z, k.z);
            fbuf[o+3] = make_float2(q.w, k.w);
        }
    }
    __syncthreads();

    // forward FFT, both series, 5 fused double-stages, ping-pong 0<->2048.
    int src = 0;
    for (int fs = 0; fs < 5; ++fs) {
        const int s  = 1 << (2 * fs);
        const int s2 = s << 1;
        const int dst = src ^ 2048;
        #pragma unroll 2
        for (int it = 0; it < 2; ++it) {
            int t  = tid + it * 256;
            int so = (t >> 8) << 10;
            int u  = t & 255;
            int j  = u & ~(s - 1);
            float2 x0 = fbuf[src + so + u];
            float2 x1 = fbuf[src + so + u + 256];
            float2 x2 = fbuf[src + so + u + 512];
            float2 x3 = fbuf[src + so + u + 768];
            float2 w0 = tw[j];
            float2 w1 = tw[j + 256];
            float2 y0 = make_float2(x0.x + x2.x, x0.y + x2.y);
            float2 dA = make_float2(x0.x - x2.x, x0.y - x2.y);
            float2 y1 = make_float2(w0.x*dA.x - w0.y*dA.y, w0.x*dA.y + w0.y*dA.x);
            float2 y2 = make_float2(x1.x + x3.x, x1.y + x3.y);
            float2 dB = make_float2(x1.x - x3.x, x1.y - x3.y);
            float2 y3 = make_float2(w1.x*dB.x - w1.y*dB.y, w1.x*dB.y + w1.y*dB.x);
            int a  = u + j;
            int ja = a & ~(s2 - 1);
            int jb = (a + s) & ~(s2 - 1);
            float2 wa = tw[ja];
            float2 wb = tw[jb];
            float2 dC = make_float2(y0.x - y2.x, y0.y - y2.y);
            fbuf[dst + so + a + ja]      = make_float2(y0.x + y2.x, y0.y + y2.y);
            fbuf[dst + so + a + ja + s2] =
                make_float2(wa.x*dC.x - wa.y*dC.y, wa.x*dC.y + wa.y*dC.x);
            float2 dD = make_float2(y1.x - y3.x, y1.y - y3.y);
            fbuf[dst + so + a + s + jb]      = make_float2(y1.x + y3.x, y1.y + y3.y);
            fbuf[dst + so + a + s + jb + s2] =
                make_float2(wb.x*dD.x - wb.y*dD.y, wb.x*dD.y + wb.y*dD.x);
        }
        __syncthreads();
        src = dst;
    }
    // forward result in [2048, 4096)

    // spectral: S = Q * conj(K); T = S_a + i*S_b; write conj(T) to [0,1024)
    for (int it = 0; it < 4; ++it) {
        int f  = tid + it * 256;
        int fn = (1024 - f) & 1023;
        float2 Za = fbuf[2048 + f],  Zan = fbuf[2048 + fn];
        float2 Zb = fbuf[3072 + f],  Zbn = fbuf[3072 + fn];
        float qx = 0.5f*(Za.x + Zan.x), qy = 0.5f*(Za.y - Zan.y);
        float kx = 0.5f*(Za.y + Zan.y), ky = -0.5f*(Za.x - Zan.x);
        float sax = qx*kx + qy*ky, say = qy*kx - qx*ky;
        float qx2 = 0.5f*(Zb.x + Zbn.x), qy2 = 0.5f*(Zb.y - Zbn.y);
        float kx2 = 0.5f*(Zb.y + Zbn.y), ky2 = -0.5f*(Zb.x - Zbn.x);
        float sbx = qx2*kx2 + qy2*ky2, sby = qy2*kx2 - qx2*ky2;
        fbuf[f] = make_float2(sax - sby, -(say + sbx));
    }
    __syncthreads();

    // load v for both series into floats [6144,8192)
    {
        const float4* va = reinterpret_cast<const float4*>(g_vp + offA);
        for (int i = tid; i < 512; i += 256)
            *reinterpret_cast<float4*>(&fbf[6144 + i * 4]) = va[i];
    }

    // inverse FFT (forward FFT of conj T), 5 fused double-stages,
    // ping-pong [0,1024) <-> [2048,3072). Ends in [2048,3072).
    int s2v = 0;
    for (int fs = 0; fs < 5; ++fs) {
        const int s  = 1 << (2 * fs);
        const int s2 = s << 1;
        const int dst = (s2v == 0) ? 2048 : 0;
        {
            int u  = tid;
            int j  = u & ~(s - 1);
            float2 x0 = fbuf[s2v + u];
            float2 x1 = fbuf[s2v + u + 256];
            float2 x2 = fbuf[s2v + u + 512];
            float2 x3 = fbuf[s2v + u + 768];
            float2 w0 = tw[j];
            float2 w1 = tw[j + 256];
            float2 y0 = make_float2(x0.x + x2.x, x0.y + x2.y);
            float2 dA = make_float2(x0.x - x2.x, x0.y - x2.y);
            float2 y1 = make_float2(w0.x*dA.x - w0.y*dA.y, w0.x*dA.y + w0.y*dA.x);
            float2 y2 = make_float2(x1.x + x3.x, x1.y + x3.y);
            float2 dB = make_float2(x1.x - x3.x, x1.y - x3.y);
            float2 y3 = make_float2(w1.x*dB.x - w1.y*dB.y, w1.x*dB.y + w1.y*dB.x);
            int a  = u + j;
            int ja = a & ~(s2 - 1);
            int jb = (a + s) & ~(s2 - 1);
            float2 wa = tw[ja];
            float2 wb = tw[jb];
            float2 dC = make_float2(y0.x - y2.x, y0.y - y2.y);
            fbuf[dst + a + ja]      = make_float2(y0.x + y2.x, y0.y + y2.y);
            fbuf[dst + a + ja + s2] =
                make_float2(wa.x*dC.x - wa.y*dC.y, wa.x*dC.y + wa.y*dC.x);
            float2 dD = make_float2(y1.x - y3.x, y1.y - y3.y);
            fbuf[dst + a + s + jb]      = make_float2(y1.x + y3.x, y1.y + y3.y);
            fbuf[dst + a + s + jb + s2] =
                make_float2(wb.x*dD.x - wb.y*dD.y, wb.x*dD.y + wb.y*dD.x);
        }
        __syncthreads();
        s2v = dst;
    }
    // result in [2048,3072): corr_a = Re/N, corr_b = -Im/N

    const float invN = 1.0f / 1024.0f;
    for (int it = 0; it < 4; ++it) {
        int n = tid + it * 256;
        float2 F = fbuf[2048 + n];
        fbf[n]        =  F.x * invN;
        fbf[1024 + n] = -F.y * invN;
    }
    __syncthreads();

    // ---- top-13, warp-local register selection ----
    const int wid5 = tid >> 5;
    const int lane = tid & 31;
    const int sidw = wid5 >> 2;
    const int ws   = wid5 & 3;
    {
        const float* scw = fbf + (sidw << 10) + ws * 256;
        float lv[8];
        #pragma unroll
        for (int j = 0; j < 8; ++j) lv[j] = scw[lane * 8 + j];
        const int gbase = ws * 256 + lane * 8;

        #pragma unroll
        for (int p = 0; p < KTOP; ++p) {
            float bv = lv[0]; int bj = 0;
            #pragma unroll
            for (int j = 1; j < 8; ++j)
                if (lv[j] > bv) { bv = lv[j]; bj = j; }
            int bi = gbase + bj;
            #pragma unroll
            for (int off = 16; off > 0; off >>= 1) {
                float ov = __shfl_xor_sync(0xffffffffu, bv, off);
                int   oi = __shfl_xor_sync(0xffffffffu, bi, off);
                if (ov > bv || (ov == bv && oi < bi)) { bv = ov; bi = oi; }
            }
            if (lane == 0) {
                candv[sidw][ws * 13 + p] = bv;
                candi[sidw][ws * 13 + p] = bi;
            }
            if (((bi - ws * 256) >> 3) == lane) lv[bi & 7] = -3.4e38f;
        }
    }
    __syncthreads();

    if (ws == 0) {
        float mv0 = (lane < 52) ? candv[sidw][lane] : -3.4e38f;
        int   mi0 = (lane < 52) ? candi[sidw][lane] : (1 << 30);
        float mv1 = (lane + 32 < 52) ? candv[sidw][lane + 32] : -3.4e38f;
        int   mi1 = (lane + 32 < 52) ? candi[sidw][lane + 32] : (1 << 30);
        #pragma unroll
        for (int p = 0; p < KTOP; ++p) {
            float bv = mv0; int bi = mi0;
            if (mv1 > bv || (mv1 == bv && mi1 < bi)) { bv = mv1; bi = mi1; }
            #pragma unroll
            for (int off = 16; off > 0; off >>= 1) {
                float ov = __shfl_xor_sync(0xffffffffu, bv, off);
                int   oi = __shfl_xor_sync(0xffffffffu, bi, off);
                if (ov > bv || (ov == bv && oi < bi)) { bv = ov; bi = oi; }
            }
            if (lane == 0) { s_tv[sidw][p] = bv; s_ti[sidw][p] = bi; }
            if (mi0 == bi) mv0 = -3.4e38f;
            if (mi1 == bi) mv1 = -3.4e38f;
        }
        if (lane == 0) {
            float mx = s_tv[sidw][0];
            float e[KTOP], sum = 0.f;
            #pragma unroll
            for (int p = 0; p < KTOP; ++p) {
                e[p] = expf(s_tv[sidw][p] - mx); sum += e[p];
            }
            float inv = 1.0f / sum;
            #pragma unroll
            for (int p = 0; p < KTOP; ++p) s_w[sidw][p] = e[p] * inv;
        }
    }
    __syncthreads();

    const int sid = tid >> 7;
    const int lt  = tid & 127;
    const float* sv = fbf + 6144 + (sid << 10);
    float* aggrow = g_agg + offA + (size_t)sid * NL;
    float wgt[KTOP]; int ix[KTOP];
    #pragma unroll
    for (int p = 0; p < KTOP; ++p) { wgt[p] = s_w[sid][p]; ix[p] = s_ti[sid][p]; }
    #pragma unroll
    for (int jj = 0; jj < 8; ++jj) {
        int l = lt + jj * 128;
        float acc = 0.f;
        #pragma unroll
        for (int p = 0; p < KTOP; ++p)
            acc += wgt[p] * sv[(l + ix[p]) & 1023];
        aggrow[l] = acc;
    }
}

// ---------------------------------------------------------------------------
// Kernel 3: transpose-broadcast agg[b][d][l] -> out[b][l][h*64+d], h=0..7.
// [l][d] staging (conflict-free LDS.128 on the store side); streaming
// stores (__stcs) + evict-first loads (__ldcs): output is never re-read.
// ---------------------------------------------------------------------------
__global__ __launch_bounds__(256) void out_kernel(float* __restrict__ out)
{
    __shared__ float t[32][68];   // [l][d], pad 4 (keeps 16B alignment)
    const int b   = blockIdx.y;
    const int l0  = blockIdx.x * 32;
    const int tid = threadIdx.x;
    const float* agg = g_agg + (size_t)b * NDH * NL;

    #pragma unroll
    for (int i = 0; i < 8; ++i) {
        int flat = tid + i * 256;   // 2048 = 64 d x 32 l
        int dd   = flat >> 5;
        int ll   = flat & 31;
        t[ll][dd] = __ldcs(agg + (size_t)dd * NL + l0 + ll);
    }
    __syncthreads();

    float* obase = out + ((size_t)b * NL + l0) * (NDH * 8);
    #pragma unroll
    for (int i = 0; i < 16; ++i) {
        int f4  = tid + i * 256;    // 4096 float4 = 32 l x 128 ch4
        int ll  = f4 >> 7;
        int c0  = (f4 & 127) * 4;
        float4 v = *reinterpret_cast<const float4*>(&t[ll][c0 & 63]);  // LDS.128
        __stcs(reinterpret_cast<float4*>(obase + (size_t)ll * 512 + c0), v);
    }
}

// ---------------------------------------------------------------------------
extern "C" void kernel_launch(void* const* d_in, const int* in_sizes, int n_in,
                              void* d_out, int out_size)
{
    const float* Q  = (const float*)d_in[0];
    const float* K  = (const float*)d_in[1];
    const float* V  = (const float*)d_in[2];
    const float* Wq = (const float*)d_in[3];
    const float* bq = (const float*)d_in[4];
    float* out = (float*)d_out;

    proj_kernel<<<dim3(NL / 128, NB, 3), 256>>>(Q, K, V, Wq, bq);
    corr_kernel<<<dim3(NDH / 2, NB), 256>>>();
    out_kernel<<<dim3(NL / 32, NB), 256>>>(out);
}

// round 17
// speedup vs baseline: 1.1445x; 1.1270x over previous
#include <cuda_runtime.h>
#include <math.h>

#define NB   16
#define NL   1024
#define ND   512
#define NDH  64
#define KTOP 13

// Scratch (no allocations allowed): 4 x 4MB fp32
__device__ float g_qp[NB * NDH * NL];   // q projection, [b][d][l]
__device__ float g_kp[NB * NDH * NL];   // k projection, [b][d][l]
__device__ float g_vp[NB * NDH * NL];   // v projection, [b][d][l]
__device__ float g_agg[NB * NDH * NL];  // aggregated result, [b][d][l]

// ---- bf16 split helpers (truncation split) --------------------------------
__device__ __forceinline__ void split_dup(float x, unsigned& wh, unsigned& wl) {
    unsigned u = __float_as_uint(x);
    float hi = __uint_as_float(u & 0xFFFF0000u);
    unsigned lu = __float_as_uint(x - hi);
    wh = __byte_perm(u,  u,  0x3232);
    wl = __byte_perm(lu, lu, 0x3232);
}
__device__ __forceinline__ unsigned split_pack(float x) {
    unsigned u = __float_as_uint(x);
    float hi = __uint_as_float(u & 0xFFFF0000u);
    unsigned lu = __float_as_uint(x - hi);
    return __byte_perm(u, lu, 0x7632);
}

__device__ __forceinline__ void mma_bf16(float* c, const unsigned* a,
                                         unsigned b0, unsigned b1) {
    asm volatile(
        "mma.sync.aligned.m16n8k16.row.col.f32.bf16.bf16.f32 "
        "{%0,%1,%2,%3}, {%4,%5,%6,%7}, {%8,%9}, {%0,%1,%2,%3};\n"
        : "+f"(c[0]), "+f"(c[1]), "+f"(c[2]), "+f"(c[3])
        : "r"(a[0]), "r"(a[1]), "r"(a[2]), "r"(a[3]), "r"(b0), "r"(b1));
}

__device__ __forceinline__ void ldsm_x4(unsigned& r0, unsigned& r1,
                                        unsigned& r2, unsigned& r3,
                                        unsigned addr) {
    asm volatile(
        "ldmatrix.sync.aligned.m8n8.x4.shared.b16 {%0,%1,%2,%3}, [%4];"
        : "=r"(r0), "=r"(r1), "=r"(r2), "=r"(r3) : "r"(addr));
}

__device__ __forceinline__ int smidx(int row, int w) {
    return row * 32 + (((w >> 3) ^ (row & 3)) << 3)
         + ((w & 7) ^ (((row >> 2) & 1) << 2));
}

// ---------------------------------------------------------------------------
// Kernel 1: projection via bf16 tensor cores, split-K doubling.
// R7 structure, but ALL fragment loads via ldmatrix.m8n8.x4 (4x fewer smem
// instructions). Thread<->fragment mapping verified identical to the scalar
// loads => bitwise-identical output. grid (NL/128, NB, 3), 256 threads.
// ---------------------------------------------------------------------------
__global__ __launch_bounds__(256) void proj_kernel(
    const float* __restrict__ Q, const float* __restrict__ K,
    const float* __restrict__ V, const float* __restrict__ Wq,
    const float* __restrict__ bq)
{
    __shared__ unsigned Ws[64 * 32];
    __shared__ unsigned Xh[128 * 32];
    __shared__ unsigned Xl[128 * 32];

    const int b    = blockIdx.y;
    const int l0   = blockIdx.x * 128;
    const int mat  = blockIdx.z;
    const int tid  = threadIdx.x;
    const int wid  = tid >> 5;
    const int lane = tid & 31;
    const int g    = lane >> 2;
    const int cq   = lane & 3;
    const int m_base = (wid >> 2) * 32;
    const int n_base = (wid & 3) * 32;

    const float* src = (mat == 0 ? Q : (mat == 1 ? K : V))
                     + ((size_t)b * NL + l0) * ND;
    float* dst = (mat == 0 ? g_qp : (mat == 1 ? g_kp : g_vp))
               + (size_t)b * NDH * NL + l0;

    const unsigned wsBase = (unsigned)__cvta_generic_to_shared(Ws);
    const unsigned xhBase = (unsigned)__cvta_generic_to_shared(Xh);
    const unsigned xlBase = (unsigned)__cvta_generic_to_shared(Xl);

    // ldmatrix lane decomposition
    const int rt = lane & 7;          // row within 8x8 tile
    const int tl = lane >> 3;         // tile index 0..3

    int xgb[4], xsb[4];
    #pragma unroll
    for (int i = 0; i < 4; ++i) {
        int f4id = tid + i * 256;
        int r    = f4id >> 3;
        int c4   = f4id & 7;
        xgb[i]   = r * ND + c4 * 4;
        xsb[i]   = r * 32 + (((c4 >> 1) ^ (r & 3)) << 3)
                 + (((c4 & 1) << 2) ^ (((r >> 2) & 1) << 2));
    }
    int wdd[2], wkq[2], wsb[2];
    #pragma unroll
    for (int i = 0; i < 2; ++i) {
        int qid = tid + i * 256;
        wdd[i]  = qid & 63;
        wkq[i]  = qid >> 6;
        wsb[i]  = wdd[i] * 32 + (((wkq[i] >> 1) ^ (wdd[i] & 3)) << 3)
                + (((wkq[i] & 1) << 2) ^ (((wdd[i] >> 2) & 1) << 2));
    }

    float acc[2][4][4];
    #pragma unroll
    for (int mt = 0; mt < 2; ++mt)
        #pragma unroll
        for (int nt = 0; nt < 4; ++nt)
            #pragma unroll
            for (int r = 0; r < 4; ++r) acc[mt][nt][r] = 0.f;

    float4 xR[4];
    float  wF[8];
    #pragma unroll
    for (int i = 0; i < 4; ++i)
        xR[i] = *reinterpret_cast<const float4*>(src + xgb[i]);
    #pragma unroll
    for (int i = 0; i < 2; ++i)
        #pragma unroll
        for (int j = 0; j < 4; ++j)
            wF[i * 4 + j] = Wq[(size_t)(wkq[i] * 4 + j) * NDH + wdd[i]];

    for (int ch = 0; ch < 16; ++ch) {
        #pragma unroll
        for (int i = 0; i < 4; ++i) {
            unsigned h0,h1,h2,h3, q0,q1,q2,q3;
            split_dup(xR[i].x, h0, q0);
            split_dup(xR[i].y, h1, q1);
            split_dup(xR[i].z, h2, q2);
            split_dup(xR[i].w, h3, q3);
            *reinterpret_cast<uint4*>(&Xh[xsb[i]]) = make_uint4(h0,h1,h2,h3);
            *reinterpret_cast<uint4*>(&Xl[xsb[i]]) = make_uint4(q0,q1,q2,q3);
        }
        #pragma unroll
        for (int i = 0; i < 2; ++i) {
            *reinterpret_cast<uint4*>(&Ws[wsb[i]]) = make_uint4(
                split_pack(wF[i*4+0]), split_pack(wF[i*4+1]),
                split_pack(wF[i*4+2]), split_pack(wF[i*4+3]));
        }
        __syncthreads();

        if (ch < 15) {
            const int ko = (ch + 1) * 32;
            #pragma unroll
            for (int i = 0; i < 4; ++i)
                xR[i] = *reinterpret_cast<const float4*>(src + xgb[i] + ko);
            #pragma unroll
            for (int i = 0; i < 2; ++i)
                #pragma unroll
                for (int j = 0; j < 4; ++j)
                    wF[i * 4 + j] = Wq[(size_t)(ko + wkq[i] * 4 + j) * NDH + wdd[i]];
        }

        #pragma unroll
        for (int ks = 0; ks < 4; ++ks) {
            const int wq0 = ks * 8;
            // A fragments: tiles (r0+{0,8} x word-quad {0,+4})
            unsigned a[2][4];
            #pragma unroll
            for (int mt = 0; mt < 2; ++mt) {
                int row = m_base + mt * 16 + ((tl & 1) << 3) + rt;
                int wq  = wq0 + ((tl >> 1) << 2);
                unsigned addr = wsBase + (unsigned)smidx(row, wq) * 4u;
                ldsm_x4(a[mt][0], a[mt][1], a[mt][2], a[mt][3], addr);
            }
            // B fragments: tiles ((nt,nt+1) x word-quad {0,+4}), both planes
            unsigned bh0[4], bh1[4], bl0[4], bl1[4];
            #pragma unroll
            for (int np = 0; np < 2; ++np) {
                int row = n_base + (np * 2 + (tl >> 1)) * 8 + rt;
                int wq  = wq0 + ((tl & 1) << 2);
                unsigned off = (unsigned)smidx(row, wq) * 4u;
                ldsm_x4(bh0[np*2], bh1[np*2], bh0[np*2+1], bh1[np*2+1],
                        xhBase + off);
                ldsm_x4(bl0[np*2], bl1[np*2], bl0[np*2+1], bl1[np*2+1],
                        xlBase + off);
            }
            // all hi-plane MMAs first (8 independent accumulators) ...
            #pragma unroll
            for (int nt = 0; nt < 4; ++nt)
                #pragma unroll
                for (int mt = 0; mt < 2; ++mt)
                    mma_bf16(acc[mt][nt], a[mt], bh0[nt], bh1[nt]);
            // ... then all lo-plane MMAs
            #pragma unroll
            for (int nt = 0; nt < 4; ++nt)
                #pragma unroll
                for (int mt = 0; mt < 2; ++mt)
                    mma_bf16(acc[mt][nt], a[mt], bl0[nt], bl1[nt]);
        }
        __syncthreads();
    }

    #pragma unroll
    for (int mt = 0; mt < 2; ++mt) {
        int d0 = m_base + mt * 16 + g;
        float bLo = bq[d0];
        float bHi = bq[d0 + 8];
        #pragma unroll
        for (int nt = 0; nt < 4; ++nt) {
            int l = n_base + nt * 8 + 2 * cq;
            float2 r0 = make_float2(acc[mt][nt][0] + bLo, acc[mt][nt][1] + bLo);
            float2 r1 = make_float2(acc[mt][nt][2] + bHi, acc[mt][nt][3] + bHi);
            *reinterpret_cast<float2*>(dst + (size_t)d0 * NL + l)       = r0;
            *reinterpret_cast<float2*>(dst + (size_t)(d0 + 8) * NL + l) = r1;
        }
    }
}

// ---------------------------------------------------------------------------
// Kernel 2: corr via FFT (reference algorithm):
//   corr = real(ifft(fft(q) * conj(fft(k))))
// Two series per CTA, 256 threads, fused radix-2^2 double stages.
// Top-13 now reads the inverse-FFT result DIRECTLY (A=Re, B=-Im; ordering
// invariant under the positive 1/N scale); 1/N folded into the softmax
// exponent. The scale pass + its barrier are removed.
// ---------------------------------------------------------------------------
__global__ __launch_bounds__(256) void corr_kernel()
{
    __shared__ __align__(16) float2 fbuf[4096];   // 32 KB workspace
    __shared__ float2 tw[512];
    __shared__ float s_tv[2][KTOP];
    __shared__ int   s_ti[2][KTOP];
    __shared__ float s_w[2][KTOP];
    __shared__ float candv[2][52];
    __shared__ int   candi[2][52];

    const int b   = blockIdx.y;
    const int d0  = blockIdx.x * 2;
    const int tid = threadIdx.x;
    float* fbf = reinterpret_cast<float*>(fbuf);
    const size_t offA = ((size_t)b * NDH + d0) * NL;

    for (int j = tid; j < 512; j += 256) {
        float s, c;
        sincospif(-(float)j / 512.0f, &s, &c);
        tw[j] = make_float2(c, s);
    }
    {
        const float4* qa = reinterpret_cast<const float4*>(g_qp + offA);
        const float4* ka = reinterpret_cast<const float4*>(g_kp + offA);
        for (int i = tid; i < 512; i += 256) {
            float4 q = qa[i], k = ka[i];
            int o = i * 4;
            fbuf[o+0] = make_float2(q.x, k.x);
            fbuf[o+1] = make_float2(q.y, k.y);
            fbuf[o+2] = make_float2(q.z, k.z);
            fbuf[o+3] = make_float2(q.w, k.w);
        }
    }
    __syncthreads();

    // forward FFT, both series, 5 fused double-stages, ping-pong 0<->2048.
    int src = 0;
    for (int fs = 0; fs < 5; ++fs) {
        const int s  = 1 << (2 * fs);
        const int s2 = s << 1;
        const int dst = src ^ 2048;
        #pragma unroll 2
        for (int it = 0; it < 2; ++it) {
            int t  = tid + it * 256;
            int so = (t >> 8) << 10;
            int u  = t & 255;
            int j  = u & ~(s - 1);
            float2 x0 = fbuf[src + so + u];
            float2 x1 = fbuf[src + so + u + 256];
            float2 x2 = fbuf[src + so + u + 512];
            float2 x3 = fbuf[src + so + u + 768];
            float2 w0 = tw[j];
            float2 w1 = tw[j + 256];
            float2 y0 = make_float2(x0.x + x2.x, x0.y + x2.y);
            float2 dA = make_float2(x0.x - x2.x, x0.y - x2.y);
            float2 y1 = make_float2(w0.x*dA.x - w0.y*dA.y, w0.x*dA.y + w0.y*dA.x);
            float2 y2 = make_float2(x1.x + x3.x, x1.y + x3.y);
            float2 dB = make_float2(x1.x - x3.x, x1.y - x3.y);
            float2 y3 = make_float2(w1.x*dB.x - w1.y*dB.y, w1.x*dB.y + w1.y*dB.x);
            int a  = u + j;
            int ja = a & ~(s2 - 1);
            int jb = (a + s) & ~(s2 - 1);
            float2 wa = tw[ja];
            float2 wb = tw[jb];
            float2 dC = make_float2(y0.x - y2.x, y0.y - y2.y);
            fbuf[dst + so + a + ja]      = make_float2(y0.x + y2.x, y0.y + y2.y);
            fbuf[dst + so + a + ja + s2] =
                make_float2(wa.x*dC.x - wa.y*dC.y, wa.x*dC.y + wa.y*dC.x);
            float2 dD = make_float2(y1.x - y3.x, y1.y - y3.y);
            fbuf[dst + so + a + s + jb]      = make_float2(y1.x + y3.x, y1.y + y3.y);
            fbuf[dst + so + a + s + jb + s2] =
                make_float2(wb.x*dD.x - wb.y*dD.y, wb.x*dD.y + wb.y*dD.x);
        }
        __syncthreads();
        src = dst;
    }
    // forward result in [2048, 4096)

    // spectral: S = Q * conj(K); T = S_a + i*S_b; write conj(T) to [0,1024)
    for (int it = 0; it < 4; ++it) {
        int f  = tid + it * 256;
        int fn = (1024 - f) & 1023;
        float2 Za = fbuf[2048 + f],  Zan = fbuf[2048 + fn];
        float2 Zb = fbuf[3072 + f],  Zbn = fbuf[3072 + fn];
        float qx = 0.5f*(Za.x + Zan.x), qy = 0.5f*(Za.y - Zan.y);
        float kx = 0.5f*(Za.y + Zan.y), ky = -0.5f*(Za.x - Zan.x);
        float sax = qx*kx + qy*ky, say = qy*kx - qx*ky;
        float qx2 = 0.5f*(Zb.x + Zbn.x), qy2 = 0.5f*(Zb.y - Zbn.y);
        float kx2 = 0.5f*(Zb.y + Zbn.y), ky2 = -0.5f*(Zb.x - Zbn.x);
        float sbx = qx2*kx2 + qy2*ky2, sby = qy2*kx2 - qx2*ky2;
        fbuf[f] = make_float2(sax - sby, -(say + sbx));
    }
    __syncthreads();

    // load v for both series into floats [6144,8192)
    {
        const float4* va = reinterpret_cast<const float4*>(g_vp + offA);
        for (int i = tid; i < 512; i += 256)
            *reinterpret_cast<float4*>(&fbf[6144 + i * 4]) = va[i];
    }

    // inverse FFT (forward FFT of conj T), 5 fused double-stages,
    // ping-pong [0,1024) <-> [2048,3072). Ends in [2048,3072).
    int s2v = 0;
    for (int fs = 0; fs < 5; ++fs) {
        const int s  = 1 << (2 * fs);
        const int s2 = s << 1;
        const int dst = (s2v == 0) ? 2048 : 0;
        {
            int u  = tid;
            int j  = u & ~(s - 1);
            float2 x0 = fbuf[s2v + u];
            float2 x1 = fbuf[s2v + u + 256];
            float2 x2 = fbuf[s2v + u + 512];
            float2 x3 = fbuf[s2v + u + 768];
            float2 w0 = tw[j];
            float2 w1 = tw[j + 256];
            float2 y0 = make_float2(x0.x + x2.x, x0.y + x2.y);
            float2 dA = make_float2(x0.x - x2.x, x0.y - x2.y);
            float2 y1 = make_float2(w0.x*dA.x - w0.y*dA.y, w0.x*dA.y + w0.y*dA.x);
            float2 y2 = make_float2(x1.x + x3.x, x1.y + x3.y);
            float2 dB = make_float2(x1.x - x3.x, x1.y - x3.y);
            float2 y3 = make_float2(w1.x*dB.x - w1.y*dB.y, w1.x*dB.y + w1.y*dB.x);
            int a  = u + j;
            int ja = a & ~(s2 - 1);
            int jb = (a + s) & ~(s2 - 1);
            float2 wa = tw[ja];
            float2 wb = tw[jb];
            float2 dC = make_float2(y0.x - y2.x, y0.y - y2.y);
            fbuf[dst + a + ja]      = make_float2(y0.x + y2.x, y0.y + y2.y);
            fbuf[dst + a + ja + s2] =
                make_float2(wa.x*dC.x - wa.y*dC.y, wa.x*dC.y + wa.y*dC.x);
            float2 dD = make_float2(y1.x - y3.x, y1.y - y3.y);
            fbuf[dst + a + s + jb]      = make_float2(y1.x + y3.x, y1.y + y3.y);
            fbuf[dst + a + s + jb + s2] =
                make_float2(wb.x*dD.x - wb.y*dD.y, wb.x*dD.y + wb.y*dD.x);
        }
        __syncthreads();
        s2v = dst;
    }
    // result in [2048,3072): corr_a = Re/N, corr_b = -Im/N (scale deferred)

    // ---- top-13, warp-local register selection on UNSCALED values ----
    const int wid5 = tid >> 5;
    const int lane = tid & 31;
    const int sidw = wid5 >> 2;
    const int ws   = wid5 & 3;
    {
        const float2* Fw = fbuf + 2048 + ws * 256 + lane * 8;
        float lv[8];
        #pragma unroll
        for (int j = 0; j < 8; ++j) {
            float2 F = Fw[j];
            lv[j] = (sidw == 0) ? F.x : -F.y;
        }
        const int gbase = ws * 256 + lane * 8;

        #pragma unroll
        for (int p = 0; p < KTOP; ++p) {
            float bv = lv[0]; int bj = 0;
            #pragma unroll
            for (int j = 1; j < 8; ++j)
                if (lv[j] > bv) { bv = lv[j]; bj = j; }
            int bi = gbase + bj;
            #pragma unroll
            for (int off = 16; off > 0; off >>= 1) {
                float ov = __shfl_xor_sync(0xffffffffu, bv, off);
                int   oi = __shfl_xor_sync(0xffffffffu, bi, off);
                if (ov > bv || (ov == bv && oi < bi)) { bv = ov; bi = oi; }
            }
            if (lane == 0) {
                candv[sidw][ws * 13 + p] = bv;
                candi[sidw][ws * 13 + p] = bi;
            }
            if (((bi - ws * 256) >> 3) == lane) lv[bi & 7] = -3.4e38f;
        }
    }
    __syncthreads();

    if (ws == 0) {
        float mv0 = (lane < 52) ? candv[sidw][lane] : -3.4e38f;
        int   mi0 = (lane < 52) ? candi[sidw][lane] : (1 << 30);
        float mv1 = (lane + 32 < 52) ? candv[sidw][lane + 32] : -3.4e38f;
        int   mi1 = (lane + 32 < 52) ? candi[sidw][lane + 32] : (1 << 30);
        #pragma unroll
        for (int p = 0; p < KTOP; ++p) {
            float bv = mv0; int bi = mi0;
            if (mv1 > bv || (mv1 == bv && mi1 < bi)) { bv = mv1; bi = mi1; }
            #pragma unroll
            for (int off = 16; off > 0; off >>= 1) {
                float ov = __shfl_xor_sync(0xffffffffu, bv, off);
                int   oi = __shfl_xor_sync(0xffffffffu, bi, off);
                if (ov > bv || (ov == bv && oi < bi)) { bv = ov; bi = oi; }
            }
            if (lane == 0) { s_tv[sidw][p] = bv; s_ti[sidw][p] = bi; }
            if (mi0 == bi) mv0 = -3.4e38f;
            if (mi1 == bi) mv1 = -3.4e38f;
        }
        if (lane == 0) {
            const float invN = 1.0f / 1024.0f;
            float mx = s_tv[sidw][0];
            float e[KTOP], sum = 0.f;
            #pragma unroll
            for (int p = 0; p < KTOP; ++p) {
                e[p] = expf((s_tv[sidw][p] - mx) * invN); sum += e[p];
            }
            float inv = 1.0f / sum;
            #pragma unroll
            for (int p = 0; p < KTOP; ++p) s_w[sidw][p] = e[p] * inv;
        }
    }
    __syncthreads();

    const int sid = tid >> 7;
    const int lt  = tid & 127;
    const float* sv = fbf + 6144 + (sid << 10);
    float* aggrow = g_agg + offA + (size_t)sid * NL;
    float wgt[KTOP]; int ix[KTOP];
    #pragma unroll
    for (int p = 0; p < KTOP; ++p) { wgt[p] = s_w[sid][p]; ix[p] = s_ti[sid][p]; }
    #pragma unroll
    for (int jj = 0; jj < 8; ++jj) {
        int l = lt + jj * 128;
        float acc = 0.f;
        #pragma unroll
        for (int p = 0; p < KTOP; ++p)
            acc += wgt[p] * sv[(l + ix[p]) & 1023];
        aggrow[l] = acc;
    }
}

// ---------------------------------------------------------------------------
// Kernel 3: transpose-broadcast agg[b][d][l] -> out[b][l][h*64+d], h=0..7.
// [l][d] staging, LDS.128 store side, streaming stores. (R16 best)
// ---------------------------------------------------------------------------
__global__ __launch_bounds__(256) void out_kernel(float* __restrict__ out)
{
    __shared__ float t[32][68];   // [l][d], pad 4 (keeps 16B alignment)
    const int b   = blockIdx.y;
    const int l0  = blockIdx.x * 32;
    const int tid = threadIdx.x;
    const float* agg = g_agg + (size_t)b * NDH * NL;

    #pragma unroll
    for (int i = 0; i < 8; ++i) {
        int flat = tid + i * 256;   // 2048 = 64 d x 32 l
        int dd   = flat >> 5;
        int ll   = flat & 31;
        t[ll][dd] = __ldcs(agg + (size_t)dd * NL + l0 + ll);
    }
    __syncthreads();

    float* obase = out + ((size_t)b * NL + l0) * (NDH * 8);
    #pragma unroll
    for (int i = 0; i < 16; ++i) {
        int f4  = tid + i * 256;    // 4096 float4 = 32 l x 128 ch4
        int ll  = f4 >> 7;
        int c0  = (f4 & 127) * 4;
        float4 v = *reinterpret_cast<const float4*>(&t[ll][c0 & 63]);  // LDS.128
        __stcs(reinterpret_cast<float4*>(obase + (size_t)ll * 512 + c0), v);
    }
}

// ---------------------------------------------------------------------------
extern "C" void kernel_launch(void* const* d_in, const int* in_sizes, int n_in,
                              void* d_out, int out_size)
{
    const float* Q  = (const float*)d_in[0];
    const float* K  = (const float*)d_in[1];
    const float* V  = (const float*)d_in[2];
    const float* Wq = (const float*)d_in[3];
    const float* bq = (const float*)d_in[4];
    float* out = (float*)d_out;

    proj_kernel<<<dim3(NL / 128, NB, 3), 256>>>(Q, K, V, Wq, bq);
    corr_kernel<<<dim3(NDH / 2, NB), 256>>>();
    out_kernel<<<dim3(NL / 32, NB), 256>>>(out);
}